// round 11
// baseline (speedup 1.0000x reference)
#include <cuda_runtime.h>
#include <cstdint>

// Problem constants
#define BATCH   16
#define TLEN    4096
#define DIMX    256
#define HID     128
#define G3      384
#define NLAYER  3
#define MROWS   (BATCH * TLEN)      // 65536

// Persistent-kernel structure
#define NBLK    148
#define RECB    32
#define GEMB    (NBLK - RECB)       // 116

// GEMM tiling
#define BM      128
#define BN      96
#define BK      16
#define NT_PER  (G3 / BN)           // 4
#define NCHUNK  (TLEN / BM)         // 32
#define TILES_PER_LAYER (2 * BATCH * NCHUNK * NT_PER)   // 4096

// Weight split: k-pairs 0..55 in registers, pairs 56..63 in shared memory
#define WREG_PAIRS 56

// -------- scratch (device globals; no runtime allocation allowed) ----------
__device__ float g_xgA[(size_t)2 * MROWS * G3];
__device__ float g_xgB[(size_t)2 * MROWS * G3];
__device__ float g_yA[(size_t)MROWS * DIMX];
__device__ float g_yB[(size_t)MROWS * DIMX];
__device__ unsigned g_fwdsteps[NLAYER][BATCH];
__device__ unsigned g_bwdsteps[NLAYER][BATCH];
__device__ unsigned g_xgready[NLAYER][2][BATCH][NCHUNK];

// ---------------- f32x2 packed helpers (Blackwell sm_103a) -----------------
__device__ __forceinline__ unsigned long long pk2(float lo, float hi) {
    unsigned long long r;
    asm("mov.b64 %0, {%1, %2};" : "=l"(r) : "f"(lo), "f"(hi));
    return r;
}
__device__ __forceinline__ void up2(unsigned long long v, float& lo, float& hi) {
    asm("mov.b64 {%0, %1}, %2;" : "=f"(lo), "=f"(hi) : "l"(v));
}
__device__ __forceinline__ unsigned long long fma2(unsigned long long a,
                                                   unsigned long long b,
                                                   unsigned long long c) {
    unsigned long long d;
    asm("fma.rn.f32x2 %0, %1, %2, %3;" : "=l"(d) : "l"(a), "l"(b), "l"(c));
    return d;
}
__device__ __forceinline__ unsigned long long fadd2(unsigned long long a,
                                                    unsigned long long b) {
    unsigned long long d;
    asm("add.rn.f32x2 %0, %1, %2;" : "=l"(d) : "l"(a), "l"(b));
    return d;
}
__device__ __forceinline__ float ex2f(float x) {
    float y; asm("ex2.approx.f32 %0, %1;" : "=f"(y) : "f"(x)); return y;
}
__device__ __forceinline__ float rcpf(float x) {
    float y; asm("rcp.approx.f32 %0, %1;" : "=f"(y) : "f"(x)); return y;
}
// sigmoid(x) = 1/(1+2^(-x*log2e))
__device__ __forceinline__ float sigmf(float x) {
    return rcpf(1.0f + ex2f(x * -1.4426950408889634f));
}
// tanh(x) = 1 - 2/(e^{2x}+1)   (exact at +-inf)
__device__ __forceinline__ float tanhf_(float x) {
    return fmaf(-2.0f, rcpf(1.0f + ex2f(x * 2.8853900817779268f)), 1.0f);
}
__device__ __forceinline__ unsigned ldv(const unsigned* p) {
    return *(volatile const unsigned*)p;
}
// forced per-step shared load (prevents ptxas hoisting weights back to regs)
__device__ __forceinline__ unsigned long long lds64(unsigned addr, int imm_off) {
    unsigned long long v;
    asm volatile("ld.shared.b64 %0, [%1];" : "=l"(v) : "r"(addr + imm_off));
    return v;
}

// -------------------------- flag reset kernel ------------------------------
__global__ void reset_flags() {
    int i = blockIdx.x * blockDim.x + threadIdx.x;
    unsigned* r = &g_xgready[0][0][0][0];
    const int nr = NLAYER * 2 * BATCH * NCHUNK;
    if (i < nr) r[i] = 0;
    if (i < NLAYER * BATCH) {
        (&g_fwdsteps[0][0])[i] = 0;
        (&g_bwdsteps[0][0])[i] = 0;
    }
}

// --------------------------- one GRU timestep ------------------------------
__device__ __forceinline__ void gru_step(
    const float*& xp, float& x0, float& x1, float*& yp, float& hp,
    long sstride, long ystride, long pf_off,
    const unsigned long long* w2, unsigned long long bias2, unsigned wbase,
    int gate, int jj, float* sh_h, float* sh_g)
{
    float x2 = __ldg(xp + pf_off);

    // matvec over all 128 h values; pairs 0..55 register weights,
    // pairs 56..63 from shared (stride 384 ulonglong = 3072 B)
    unsigned long long a0 = bias2, a1 = 0ULL;
    const ulonglong2* h2 = (const ulonglong2*)sh_h;
#pragma unroll
    for (int i = 0; i < WREG_PAIRS / 2; i++) {
        ulonglong2 hv = h2[i];
        a0 = fma2(hv.x, w2[2 * i],     a0);
        a1 = fma2(hv.y, w2[2 * i + 1], a1);
    }
#pragma unroll
    for (int i = 0; i < 4; i++) {
        ulonglong2 hv = h2[WREG_PAIRS / 2 + i];
        unsigned long long ws0 = lds64(wbase, (2 * i) * 3072);
        unsigned long long ws1 = lds64(wbase, (2 * i + 1) * 3072);
        a0 = fma2(hv.x, ws0, a0);
        a1 = fma2(hv.y, ws1, a1);
    }
    a0 = fadd2(a0, a1);
    float lo_, hi_;
    up2(a0, lo_, hi_);
    const float q = lo_ + hi_;   // hdot + bias

    if (gate < 2) sh_g[gate * HID + jj] = sigmf(x0 + q);
    __syncthreads();

    if (gate == 2) {
        float r_ = sh_g[jj];
        float z_ = sh_g[HID + jj];
        float n_ = tanhf_(fmaf(r_, q, x0));
        float hn = fmaf(z_, hp - n_, n_);
        hp = hn;
        sh_h[jj] = hn;
        *yp = hn;
    }
    __syncthreads();

    x0 = x1;
    x1 = x2;
    xp += sstride;
    yp += ystride;
}

// ------------------------- persistent fused kernel -------------------------
__global__ void __launch_bounds__(384, 1)
fused_birnn(const float* __restrict__ xin,
            const float* __restrict__ Wi,   // [3][2][256][384]
            const float* __restrict__ Wh,   // [3][2][128][384]
            const float* __restrict__ bh,   // [3][2][384]
            float* __restrict__ out) {
    __shared__ __align__(16) float sh_As[2][BK][BM + 4];
    __shared__ __align__(16) unsigned long long sh_Bs[2][BK][BN];
    __shared__ __align__(16) float sh_h[HID];
    __shared__ __align__(16) float sh_g[2 * HID];           // [r | z]
    __shared__ __align__(16) unsigned long long sh_w[8][G3]; // spill-relief weights

    const int tid = threadIdx.x;

    if (blockIdx.x < RECB) {
        // ================= RECURRENCE ROLE (blocks 0..31) ==================
        const int d = blockIdx.x >> 4;
        const int b = blockIdx.x & 15;
        const int j = tid;
        const int gate = j >> 7;
        const int jj = j & 127;
        const int dt = d ? -1 : 1;
        const long sstride = (long)dt * G3;
        const long ystride = (long)dt * DIMX;
        const unsigned wbase =
            (unsigned)__cvta_generic_to_shared(&sh_w[0][j]);

        for (int l = 0; l < NLAYER; l++) {
            const float* Wd = Wh + (size_t)(l * 2 + d) * HID * G3;
            const unsigned long long bias2 =
                pk2(bh[(l * 2 + d) * G3 + j], 0.0f);
            const float* xgbuf = (l == 1) ? g_xgB : g_xgA;
            const float* xgb = xgbuf + ((size_t)d * MROWS + (size_t)b * TLEN) * G3;
            float* yo = (l == 0) ? g_yA : (l == 1) ? g_yB : out;
            const unsigned* rdy = &g_xgready[l][d][b][0];

            // register-resident weight pairs 0..55 (h rows 0..111)
            unsigned long long w2[WREG_PAIRS];
#pragma unroll
            for (int i = 0; i < WREG_PAIRS; i++)
                w2[i] = pk2(Wd[(2 * i) * G3 + j], Wd[(2 * i + 1) * G3 + j]);
            // shared-resident pairs 56..63 (h rows 112..127)
#pragma unroll
            for (int p = 0; p < 8; p++)
                sh_w[p][j] = pk2(Wd[(2 * (WREG_PAIRS + p)) * G3 + j],
                                 Wd[(2 * (WREG_PAIRS + p) + 1) * G3 + j]);

            if (j < HID) sh_h[j] = 0.0f;

            // wait for first consumed chunk
            {
                const int c0 = d ? (NCHUNK - 1) : 0;
                if (j == 0) {
                    while (ldv(&rdy[c0]) < NT_PER) __nanosleep(64);
                }
            }
            __syncthreads();
            __threadfence();

            const int t0 = d ? (TLEN - 1) : 0;
            const float* xp = xgb + (size_t)t0 * G3 + j;
            float x0 = __ldg(xp);
            float x1 = __ldg(xp + sstride);
            float* yp = yo + (size_t)b * TLEN * DIMX + (size_t)t0 * DIMX
                        + d * HID + jj;
            float hp = 0.0f;
            unsigned done = 0;

            for (int c = 0; c < NCHUNK; c++) {
                // 126 steps whose distance-2 prefetch stays inside chunk c
                for (int u = 0; u < 126; u++) {
                    gru_step(xp, x0, x1, yp, hp, sstride, ystride, 2 * sstride,
                             w2, bias2, wbase, gate, jj, sh_h, sh_g);
                }
                if (c < NCHUNK - 1) {
                    const int cn = d ? (NCHUNK - 2 - c) : (c + 1);
                    if (j == 0) {
                        while (ldv(&rdy[cn]) < NT_PER) __nanosleep(64);
                    }
                    __syncthreads();
                    __threadfence();
                    gru_step(xp, x0, x1, yp, hp, sstride, ystride, 2 * sstride,
                             w2, bias2, wbase, gate, jj, sh_h, sh_g);
                    gru_step(xp, x0, x1, yp, hp, sstride, ystride, 2 * sstride,
                             w2, bias2, wbase, gate, jj, sh_h, sh_g);
                } else {
                    gru_step(xp, x0, x1, yp, hp, sstride, ystride, 0,
                             w2, bias2, wbase, gate, jj, sh_h, sh_g);
                    gru_step(xp, x0, x1, yp, hp, sstride, ystride, 0,
                             w2, bias2, wbase, gate, jj, sh_h, sh_g);
                }
                done += BM;
                if (j == 0) {
                    __threadfence();
                    *(volatile unsigned*)(d ? &g_bwdsteps[l][b]
                                            : &g_fwdsteps[l][b]) = done;
                }
            }
        }
    } else {
        // =================== GEMM ROLE (blocks 32..147) ====================
        const int gid = blockIdx.x - RECB;
        const int ty8 = (tid / 24) * 8;
        const int tx4 = (tid % 24) * 4;
        const int arow = tid >> 2;
        const int ak = (tid & 3) << 2;
        const int brow = tid / 24;
        const int bc = (tid % 24) * 4;

        for (int l = 0; l < NLAYER; l++) {
            const float* Asrc = (l == 0) ? xin : (l == 1) ? g_yA : g_yB;
            float* xgdst = (l == 1) ? g_xgB : g_xgA;
            const float* Wl = Wi + (size_t)l * 2 * DIMX * G3;

            for (int rank = gid; rank < TILES_PER_LAYER; rank += GEMB) {
                const int o = rank >> 7;
                const int rem = rank & 127;
                const int dir = rem >> 6;
                const int b = (rem >> 2) & 15;
                const int nt = rem & 3;
                int ci;
                if (l == 0)
                    ci = (o & 1) ? (NCHUNK - 1 - (o >> 1)) : (o >> 1);
                else
                    ci = (o & 1) ? (NCHUNK / 2 + (o >> 1))
                                 : (NCHUNK / 2 - 1 - (o >> 1));

                if (l > 0) {
                    if (tid == 0) {
                        unsigned needf = (unsigned)((ci + 1) * BM);
                        unsigned needb = (unsigned)(TLEN - ci * BM);
                        while (ldv(&g_fwdsteps[l - 1][b]) < needf) __nanosleep(128);
                        while (ldv(&g_bwdsteps[l - 1][b]) < needb) __nanosleep(128);
                    }
                    __syncthreads();
                    __threadfence();
                }

                const float* At = Asrc + ((size_t)b * TLEN + (size_t)ci * BM) * DIMX;
                const float* Bt = Wl + (size_t)dir * DIMX * G3 + nt * BN;
                float* Ct = xgdst + (size_t)dir * MROWS * G3 +
                            ((size_t)b * TLEN + (size_t)ci * BM) * G3 + nt * BN;

                unsigned long long acc[4][4];
#pragma unroll
                for (int i = 0; i < 4; i++)
#pragma unroll
                    for (int q = 0; q < 4; q++) acc[i][q] = 0ULL;

                float4 a0r = *(const float4*)&At[(size_t)arow * DIMX + ak];
                float4 a1r = make_float4(0.f, 0.f, 0.f, 0.f);
                if (tid < 128)
                    a1r = *(const float4*)&At[(size_t)(arow + 96) * DIMX + ak];
                float4 b0r = *(const float4*)&Bt[(size_t)brow * G3 + bc];

                sh_As[0][ak + 0][arow] = a0r.x;
                sh_As[0][ak + 1][arow] = a0r.y;
                sh_As[0][ak + 2][arow] = a0r.z;
                sh_As[0][ak + 3][arow] = a0r.w;
                if (tid < 128) {
                    sh_As[0][ak + 0][arow + 96] = a1r.x;
                    sh_As[0][ak + 1][arow + 96] = a1r.y;
                    sh_As[0][ak + 2][arow + 96] = a1r.z;
                    sh_As[0][ak + 3][arow + 96] = a1r.w;
                }
                {
                    ulonglong2 bp0, bp1;
                    bp0.x = pk2(b0r.x, b0r.x); bp0.y = pk2(b0r.y, b0r.y);
                    bp1.x = pk2(b0r.z, b0r.z); bp1.y = pk2(b0r.w, b0r.w);
                    *(ulonglong2*)&sh_Bs[0][brow][bc] = bp0;
                    *(ulonglong2*)&sh_Bs[0][brow][bc + 2] = bp1;
                }
                __syncthreads();

                for (int cc = 0; cc < DIMX / BK; cc++) {
                    const int cur = cc & 1;
                    if (cc < DIMX / BK - 1) {
                        const int k0 = (cc + 1) * BK;
                        a0r = *(const float4*)&At[(size_t)arow * DIMX + k0 + ak];
                        if (tid < 128)
                            a1r = *(const float4*)&At[(size_t)(arow + 96) * DIMX + k0 + ak];
                        b0r = *(const float4*)&Bt[(size_t)(k0 + brow) * G3 + bc];
                    }
#pragma unroll
                    for (int k = 0; k < BK; k++) {
                        const float* Ak = &sh_As[cur][k][ty8];
                        ulonglong2 av0 = *(const ulonglong2*)(Ak);
                        ulonglong2 av1 = *(const ulonglong2*)(Ak + 4);
                        const unsigned long long* Bk = &sh_Bs[cur][k][tx4];
                        ulonglong2 bv0 = *(const ulonglong2*)(Bk);
                        ulonglong2 bv1 = *(const ulonglong2*)(Bk + 2);
                        acc[0][0] = fma2(av0.x, bv0.x, acc[0][0]);
                        acc[0][1] = fma2(av0.x, bv0.y, acc[0][1]);
                        acc[0][2] = fma2(av0.x, bv1.x, acc[0][2]);
                        acc[0][3] = fma2(av0.x, bv1.y, acc[0][3]);
                        acc[1][0] = fma2(av0.y, bv0.x, acc[1][0]);
                        acc[1][1] = fma2(av0.y, bv0.y, acc[1][1]);
                        acc[1][2] = fma2(av0.y, bv1.x, acc[1][2]);
                        acc[1][3] = fma2(av0.y, bv1.y, acc[1][3]);
                        acc[2][0] = fma2(av1.x, bv0.x, acc[2][0]);
                        acc[2][1] = fma2(av1.x, bv0.y, acc[2][1]);
                        acc[2][2] = fma2(av1.x, bv1.x, acc[2][2]);
                        acc[2][3] = fma2(av1.x, bv1.y, acc[2][3]);
                        acc[3][0] = fma2(av1.y, bv0.x, acc[3][0]);
                        acc[3][1] = fma2(av1.y, bv0.y, acc[3][1]);
                        acc[3][2] = fma2(av1.y, bv1.x, acc[3][2]);
                        acc[3][3] = fma2(av1.y, bv1.y, acc[3][3]);
                    }
                    if (cc < DIMX / BK - 1) {
                        const int nxt = cur ^ 1;
                        sh_As[nxt][ak + 0][arow] = a0r.x;
                        sh_As[nxt][ak + 1][arow] = a0r.y;
                        sh_As[nxt][ak + 2][arow] = a0r.z;
                        sh_As[nxt][ak + 3][arow] = a0r.w;
                        if (tid < 128) {
                            sh_As[nxt][ak + 0][arow + 96] = a1r.x;
                            sh_As[nxt][ak + 1][arow + 96] = a1r.y;
                            sh_As[nxt][ak + 2][arow + 96] = a1r.z;
                            sh_As[nxt][ak + 3][arow + 96] = a1r.w;
                        }
                        ulonglong2 bp0, bp1;
                        bp0.x = pk2(b0r.x, b0r.x); bp0.y = pk2(b0r.y, b0r.y);
                        bp1.x = pk2(b0r.z, b0r.z); bp1.y = pk2(b0r.w, b0r.w);
                        *(ulonglong2*)&sh_Bs[nxt][brow][bc] = bp0;
                        *(ulonglong2*)&sh_Bs[nxt][brow][bc + 2] = bp1;
                        __syncthreads();
                    }
                }

#pragma unroll
                for (int mp = 0; mp < 4; mp++) {
                    float l0, h0, l1, h1, l2, h2, l3, h3;
                    up2(acc[mp][0], l0, h0);
                    up2(acc[mp][1], l1, h1);
                    up2(acc[mp][2], l2, h2);
                    up2(acc[mp][3], l3, h3);
                    const int row = ty8 + 2 * mp;
                    *(float4*)&Ct[(size_t)row * G3 + tx4] =
                        make_float4(l0, l1, l2, l3);
                    *(float4*)&Ct[(size_t)(row + 1) * G3 + tx4] =
                        make_float4(h0, h1, h2, h3);
                }
                __syncthreads();
                if (tid == 0) {
                    __threadfence();
                    atomicAdd(&g_xgready[l][dir][b][ci], 1u);
                }
                __syncthreads();
            }
        }
    }
}

// ---------------------------------------------------------------------------
extern "C" void kernel_launch(void* const* d_in, const int* in_sizes, int n_in,
                              void* d_out, int out_size) {
    const float* x  = (const float*)d_in[0];
    const float* Wi = (const float*)d_in[1];
    const float* Wh = (const float*)d_in[2];
    const float* bh = (const float*)d_in[3];
    float* out = (float*)d_out;

    reset_flags<<<(NLAYER * 2 * BATCH * NCHUNK + 255) / 256, 256>>>();
    fused_birnn<<<NBLK, 384>>>(x, Wi, Wh, bh, out);
}

// round 12
// speedup vs baseline: 1.0599x; 1.0599x over previous
#include <cuda_runtime.h>
#include <cstdint>

// Problem constants
#define BATCH   16
#define TLEN    4096
#define DIMX    256
#define HID     128
#define G3      384
#define NLAYER  3
#define MROWS   (BATCH * TLEN)      // 65536

// Persistent-kernel structure
#define NBLK    148
#define RECB    32
#define GEMB    (NBLK - RECB)       // 116

// GEMM tiling
#define BM      128
#define BN      96
#define BK      16
#define NT_PER  (G3 / BN)           // 4
#define NCHUNK  (TLEN / BM)         // 32
#define TILES_PER_LAYER (2 * BATCH * NCHUNK * NT_PER)   // 4096

// -------- scratch (device globals; no runtime allocation allowed) ----------
__device__ float g_xgA[(size_t)2 * MROWS * G3];
__device__ float g_xgB[(size_t)2 * MROWS * G3];
__device__ float g_yA[(size_t)MROWS * DIMX];
__device__ float g_yB[(size_t)MROWS * DIMX];
__device__ unsigned g_fwdsteps[NLAYER][BATCH];
__device__ unsigned g_bwdsteps[NLAYER][BATCH];
__device__ unsigned g_xgready[NLAYER][2][BATCH][NCHUNK];

// ---------------- f32x2 packed helpers (Blackwell sm_103a) -----------------
__device__ __forceinline__ unsigned long long pk2(float lo, float hi) {
    unsigned long long r;
    asm("mov.b64 %0, {%1, %2};" : "=l"(r) : "f"(lo), "f"(hi));
    return r;
}
__device__ __forceinline__ void up2(unsigned long long v, float& lo, float& hi) {
    asm("mov.b64 {%0, %1}, %2;" : "=f"(lo), "=f"(hi) : "l"(v));
}
__device__ __forceinline__ unsigned long long fma2(unsigned long long a,
                                                   unsigned long long b,
                                                   unsigned long long c) {
    unsigned long long d;
    asm("fma.rn.f32x2 %0, %1, %2, %3;" : "=l"(d) : "l"(a), "l"(b), "l"(c));
    return d;
}
__device__ __forceinline__ unsigned long long fadd2(unsigned long long a,
                                                    unsigned long long b) {
    unsigned long long d;
    asm("add.rn.f32x2 %0, %1, %2;" : "=l"(d) : "l"(a), "l"(b));
    return d;
}
__device__ __forceinline__ float ex2f(float x) {
    float y; asm("ex2.approx.f32 %0, %1;" : "=f"(y) : "f"(x)); return y;
}
__device__ __forceinline__ float rcpf(float x) {
    float y; asm("rcp.approx.f32 %0, %1;" : "=f"(y) : "f"(x)); return y;
}
// sigmoid(x) = 1/(1+2^(-x*log2e))
__device__ __forceinline__ float sigmf(float x) {
    return rcpf(1.0f + ex2f(x * -1.4426950408889634f));
}
// tanh(x) = 1 - 2/(e^{2x}+1)   (exact at +-inf)
__device__ __forceinline__ float tanhf_(float x) {
    return fmaf(-2.0f, rcpf(1.0f + ex2f(x * 2.8853900817779268f)), 1.0f);
}
__device__ __forceinline__ unsigned ldv(const unsigned* p) {
    return *(volatile const unsigned*)p;
}

// -------------------------- flag reset kernel ------------------------------
__global__ void reset_flags() {
    int i = blockIdx.x * blockDim.x + threadIdx.x;
    unsigned* r = &g_xgready[0][0][0][0];
    const int nr = NLAYER * 2 * BATCH * NCHUNK;
    if (i < nr) r[i] = 0;
    if (i < NLAYER * BATCH) {
        (&g_fwdsteps[0][0])[i] = 0;
        (&g_bwdsteps[0][0])[i] = 0;
    }
}

// --------------------------- one GRU timestep ------------------------------
// Warp-priority mapping: n-gate threads are tid 0..127 (LOWEST wid =>
// lowest arbiter priority), r/z threads tid 128..383 (higher priority).
// r/z therefore finish matvec+sigmoid before n-threads drain, so the
// post-barrier tail starts with r/z already written.
__device__ __forceinline__ void gru_step(
    const float*& xp, float& x0, float& x1, float*& yp, float& hp,
    long sstride, long ystride, long pf_off,
    const unsigned long long* w2, unsigned long long bias2,
    bool isN, int gslot, int jj, float* sh_h, float* sh_g)
{
    float x2 = __ldg(xp + pf_off);

    // matvec over all 128 h values (bias pre-folded into a0)
    unsigned long long a0 = bias2, a1 = 0ULL;
    const ulonglong2* h2 = (const ulonglong2*)sh_h;
#pragma unroll
    for (int i = 0; i < 32; i++) {
        ulonglong2 hv = h2[i];
        a0 = fma2(hv.x, w2[2 * i],     a0);
        a1 = fma2(hv.y, w2[2 * i + 1], a1);
    }
    a0 = fadd2(a0, a1);
    float lo_, hi_;
    up2(a0, lo_, hi_);
    const float q = lo_ + hi_;   // hdot + bias

    if (!isN) sh_g[gslot] = sigmf(x0 + q);
    __syncthreads();

    if (isN) {
        float r_ = sh_g[jj];
        float z_ = sh_g[HID + jj];
        float n_ = tanhf_(fmaf(r_, q, x0));
        float hn = fmaf(z_, hp - n_, n_);
        hp = hn;
        sh_h[jj] = hn;
        *yp = hn;
    }
    __syncthreads();

    x0 = x1;
    x1 = x2;
    xp += sstride;
    yp += ystride;
}

// ------------------------- persistent fused kernel -------------------------
__global__ void __launch_bounds__(384, 1)
fused_birnn(const float* __restrict__ xin,
            const float* __restrict__ Wi,   // [3][2][256][384]
            const float* __restrict__ Wh,   // [3][2][128][384]
            const float* __restrict__ bh,   // [3][2][384]
            float* __restrict__ out) {
    __shared__ __align__(16) float sh_As[2][BK][BM + 4];
    __shared__ __align__(16) unsigned long long sh_Bs[2][BK][BN];
    __shared__ __align__(16) float sh_h[HID];
    __shared__ __align__(16) float sh_g[2 * HID];   // [r | z]

    const int tid = threadIdx.x;

    if (blockIdx.x < RECB) {
        // ================= RECURRENCE ROLE (blocks 0..31) ==================
        const int d = blockIdx.x >> 4;
        const int b = blockIdx.x & 15;
        // Gate remap: tid<128 -> n-gate (col 256+tid); tid>=128 -> r/z
        // (col tid-128: r for tid<256, z for tid>=256).
        const bool isN = (tid < 128);
        const int col = isN ? (tid + 256) : (tid - 128);
        const int jj = col & 127;
        const int gslot = (tid >= 256) ? (HID + jj) : jj;  // r/z smem slot
        const int dt = d ? -1 : 1;
        const long sstride = (long)dt * G3;
        const long ystride = (long)dt * DIMX;

        for (int l = 0; l < NLAYER; l++) {
            const float* Wd = Wh + (size_t)(l * 2 + d) * HID * G3;
            const unsigned long long bias2 =
                pk2(bh[(l * 2 + d) * G3 + col], 0.0f);
            const float* xgbuf = (l == 1) ? g_xgB : g_xgA;
            const float* xgb = xgbuf + ((size_t)d * MROWS + (size_t)b * TLEN) * G3;
            float* yo = (l == 0) ? g_yA : (l == 1) ? g_yB : out;
            const unsigned* rdy = &g_xgready[l][d][b][0];

            unsigned long long w2[64];
#pragma unroll
            for (int i = 0; i < 64; i++)
                w2[i] = pk2(Wd[(2 * i) * G3 + col], Wd[(2 * i + 1) * G3 + col]);

            if (tid < HID) sh_h[tid] = 0.0f;

            // wait for first consumed chunk
            {
                const int c0 = d ? (NCHUNK - 1) : 0;
                if (tid == 0) {
                    while (ldv(&rdy[c0]) < NT_PER) __nanosleep(64);
                }
            }
            __syncthreads();
            __threadfence();

            const int t0 = d ? (TLEN - 1) : 0;
            const float* xp = xgb + (size_t)t0 * G3 + col;
            float x0 = __ldg(xp);
            float x1 = __ldg(xp + sstride);
            float* yp = yo + (size_t)b * TLEN * DIMX + (size_t)t0 * DIMX
                        + d * HID + jj;
            float hp = 0.0f;
            unsigned done = 0;

            for (int c = 0; c < NCHUNK; c++) {
                // 126 steps whose distance-2 prefetch stays inside chunk c
                for (int u = 0; u < 126; u++) {
                    gru_step(xp, x0, x1, yp, hp, sstride, ystride, 2 * sstride,
                             w2, bias2, isN, gslot, jj, sh_h, sh_g);
                }
                if (c < NCHUNK - 1) {
                    const int cn = d ? (NCHUNK - 2 - c) : (c + 1);
                    if (tid == 0) {
                        while (ldv(&rdy[cn]) < NT_PER) __nanosleep(64);
                    }
                    __syncthreads();
                    __threadfence();
                    gru_step(xp, x0, x1, yp, hp, sstride, ystride, 2 * sstride,
                             w2, bias2, isN, gslot, jj, sh_h, sh_g);
                    gru_step(xp, x0, x1, yp, hp, sstride, ystride, 2 * sstride,
                             w2, bias2, isN, gslot, jj, sh_h, sh_g);
                } else {
                    gru_step(xp, x0, x1, yp, hp, sstride, ystride, 0,
                             w2, bias2, isN, gslot, jj, sh_h, sh_g);
                    gru_step(xp, x0, x1, yp, hp, sstride, ystride, 0,
                             w2, bias2, isN, gslot, jj, sh_h, sh_g);
                }
                done += BM;
                if (tid == 0) {
                    __threadfence();
                    *(volatile unsigned*)(d ? &g_bwdsteps[l][b]
                                            : &g_fwdsteps[l][b]) = done;
                }
            }
        }
    } else {
        // =================== GEMM ROLE (blocks 32..147) ====================
        const int gid = blockIdx.x - RECB;
        const int ty8 = (tid / 24) * 8;
        const int tx4 = (tid % 24) * 4;
        const int arow = tid >> 2;
        const int ak = (tid & 3) << 2;
        const int brow = tid / 24;
        const int bc = (tid % 24) * 4;

        for (int l = 0; l < NLAYER; l++) {
            const float* Asrc = (l == 0) ? xin : (l == 1) ? g_yA : g_yB;
            float* xgdst = (l == 1) ? g_xgB : g_xgA;
            const float* Wl = Wi + (size_t)l * 2 * DIMX * G3;

            for (int rank = gid; rank < TILES_PER_LAYER; rank += GEMB) {
                const int o = rank >> 7;
                const int rem = rank & 127;
                const int dir = rem >> 6;
                const int b = (rem >> 2) & 15;
                const int nt = rem & 3;
                int ci;
                if (l == 0)
                    ci = (o & 1) ? (NCHUNK - 1 - (o >> 1)) : (o >> 1);
                else
                    ci = (o & 1) ? (NCHUNK / 2 + (o >> 1))
                                 : (NCHUNK / 2 - 1 - (o >> 1));

                if (l > 0) {
                    if (tid == 0) {
                        unsigned needf = (unsigned)((ci + 1) * BM);
                        unsigned needb = (unsigned)(TLEN - ci * BM);
                        while (ldv(&g_fwdsteps[l - 1][b]) < needf) __nanosleep(128);
                        while (ldv(&g_bwdsteps[l - 1][b]) < needb) __nanosleep(128);
                    }
                    __syncthreads();
                    __threadfence();
                }

                const float* At = Asrc + ((size_t)b * TLEN + (size_t)ci * BM) * DIMX;
                const float* Bt = Wl + (size_t)dir * DIMX * G3 + nt * BN;
                float* Ct = xgdst + (size_t)dir * MROWS * G3 +
                            ((size_t)b * TLEN + (size_t)ci * BM) * G3 + nt * BN;

                unsigned long long acc[4][4];
#pragma unroll
                for (int i = 0; i < 4; i++)
#pragma unroll
                    for (int q = 0; q < 4; q++) acc[i][q] = 0ULL;

                float4 a0r = *(const float4*)&At[(size_t)arow * DIMX + ak];
                float4 a1r = make_float4(0.f, 0.f, 0.f, 0.f);
                if (tid < 128)
                    a1r = *(const float4*)&At[(size_t)(arow + 96) * DIMX + ak];
                float4 b0r = *(const float4*)&Bt[(size_t)brow * G3 + bc];

                sh_As[0][ak + 0][arow] = a0r.x;
                sh_As[0][ak + 1][arow] = a0r.y;
                sh_As[0][ak + 2][arow] = a0r.z;
                sh_As[0][ak + 3][arow] = a0r.w;
                if (tid < 128) {
                    sh_As[0][ak + 0][arow + 96] = a1r.x;
                    sh_As[0][ak + 1][arow + 96] = a1r.y;
                    sh_As[0][ak + 2][arow + 96] = a1r.z;
                    sh_As[0][ak + 3][arow + 96] = a1r.w;
                }
                {
                    ulonglong2 bp0, bp1;
                    bp0.x = pk2(b0r.x, b0r.x); bp0.y = pk2(b0r.y, b0r.y);
                    bp1.x = pk2(b0r.z, b0r.z); bp1.y = pk2(b0r.w, b0r.w);
                    *(ulonglong2*)&sh_Bs[0][brow][bc] = bp0;
                    *(ulonglong2*)&sh_Bs[0][brow][bc + 2] = bp1;
                }
                __syncthreads();

                for (int cc = 0; cc < DIMX / BK; cc++) {
                    const int cur = cc & 1;
                    if (cc < DIMX / BK - 1) {
                        const int k0 = (cc + 1) * BK;
                        a0r = *(const float4*)&At[(size_t)arow * DIMX + k0 + ak];
                        if (tid < 128)
                            a1r = *(const float4*)&At[(size_t)(arow + 96) * DIMX + k0 + ak];
                        b0r = *(const float4*)&Bt[(size_t)(k0 + brow) * G3 + bc];
                    }
#pragma unroll
                    for (int k = 0; k < BK; k++) {
                        const float* Ak = &sh_As[cur][k][ty8];
                        ulonglong2 av0 = *(const ulonglong2*)(Ak);
                        ulonglong2 av1 = *(const ulonglong2*)(Ak + 4);
                        const unsigned long long* Bk = &sh_Bs[cur][k][tx4];
                        ulonglong2 bv0 = *(const ulonglong2*)(Bk);
                        ulonglong2 bv1 = *(const ulonglong2*)(Bk + 2);
                        acc[0][0] = fma2(av0.x, bv0.x, acc[0][0]);
                        acc[0][1] = fma2(av0.x, bv0.y, acc[0][1]);
                        acc[0][2] = fma2(av0.x, bv1.x, acc[0][2]);
                        acc[0][3] = fma2(av0.x, bv1.y, acc[0][3]);
                        acc[1][0] = fma2(av0.y, bv0.x, acc[1][0]);
                        acc[1][1] = fma2(av0.y, bv0.y, acc[1][1]);
                        acc[1][2] = fma2(av0.y, bv1.x, acc[1][2]);
                        acc[1][3] = fma2(av0.y, bv1.y, acc[1][3]);
                        acc[2][0] = fma2(av1.x, bv0.x, acc[2][0]);
                        acc[2][1] = fma2(av1.x, bv0.y, acc[2][1]);
                        acc[2][2] = fma2(av1.x, bv1.x, acc[2][2]);
                        acc[2][3] = fma2(av1.x, bv1.y, acc[2][3]);
                        acc[3][0] = fma2(av1.y, bv0.x, acc[3][0]);
                        acc[3][1] = fma2(av1.y, bv0.y, acc[3][1]);
                        acc[3][2] = fma2(av1.y, bv1.x, acc[3][2]);
                        acc[3][3] = fma2(av1.y, bv1.y, acc[3][3]);
                    }
                    if (cc < DIMX / BK - 1) {
                        const int nxt = cur ^ 1;
                        sh_As[nxt][ak + 0][arow] = a0r.x;
                        sh_As[nxt][ak + 1][arow] = a0r.y;
                        sh_As[nxt][ak + 2][arow] = a0r.z;
                        sh_As[nxt][ak + 3][arow] = a0r.w;
                        if (tid < 128) {
                            sh_As[nxt][ak + 0][arow + 96] = a1r.x;
                            sh_As[nxt][ak + 1][arow + 96] = a1r.y;
                            sh_As[nxt][ak + 2][arow + 96] = a1r.z;
                            sh_As[nxt][ak + 3][arow + 96] = a1r.w;
                        }
                        ulonglong2 bp0, bp1;
                        bp0.x = pk2(b0r.x, b0r.x); bp0.y = pk2(b0r.y, b0r.y);
                        bp1.x = pk2(b0r.z, b0r.z); bp1.y = pk2(b0r.w, b0r.w);
                        *(ulonglong2*)&sh_Bs[nxt][brow][bc] = bp0;
                        *(ulonglong2*)&sh_Bs[nxt][brow][bc + 2] = bp1;
                        __syncthreads();
                    }
                }

#pragma unroll
                for (int mp = 0; mp < 4; mp++) {
                    float l0, h0, l1, h1, l2, h2, l3, h3;
                    up2(acc[mp][0], l0, h0);
                    up2(acc[mp][1], l1, h1);
                    up2(acc[mp][2], l2, h2);
                    up2(acc[mp][3], l3, h3);
                    const int row = ty8 + 2 * mp;
                    *(float4*)&Ct[(size_t)row * G3 + tx4] =
                        make_float4(l0, l1, l2, l3);
                    *(float4*)&Ct[(size_t)(row + 1) * G3 + tx4] =
                        make_float4(h0, h1, h2, h3);
                }
                __syncthreads();
                if (tid == 0) {
                    __threadfence();
                    atomicAdd(&g_xgready[l][dir][b][ci], 1u);
                }
                __syncthreads();
            }
        }
    }
}

// ---------------------------------------------------------------------------
extern "C" void kernel_launch(void* const* d_in, const int* in_sizes, int n_in,
                              void* d_out, int out_size) {
    const float* x  = (const float*)d_in[0];
    const float* Wi = (const float*)d_in[1];
    const float* Wh = (const float*)d_in[2];
    const float* bh = (const float*)d_in[3];
    float* out = (float*)d_out;

    reset_flags<<<(NLAYER * 2 * BATCH * NCHUNK + 255) / 256, 256>>>();
    fused_birnn<<<NBLK, 384>>>(x, Wi, Wh, bh, out);
}